// round 2
// baseline (speedup 1.0000x reference)
#include <cuda_runtime.h>
#include <cuda_bf16.h>

// Top-k mask via single-pass 8192-bin radix histogram + candidate compaction.
// Keys = fp32 bits of |x| (order-isomorphic for non-negative floats).
// Stage 1: histogram bits 29..17 (full read).  Stage 2 (fused with mask
// write): compact (key,idx) of threshold-bin elements (~n/128).  Stage 3:
// single-block select of remaining 17 bits over compacted candidates +
// exact stable-argsort tie fixup.

#define NB1     8192
#define SHIFT1  17
#define CAND_CAP (1u << 21)
#define BLK_CAP  4096
#define EQ_CAP   4096

__device__ unsigned g_hist[NB1];
__device__ unsigned g_binT;
__device__ unsigned g_rank;
__device__ unsigned g_cand_idx[CAND_CAP];
__device__ unsigned g_cand_key[CAND_CAP];
__device__ unsigned g_cand_cnt;

__device__ __forceinline__ unsigned abskey(float v) {
    return __float_as_uint(v) & 0x7FFFFFFFu;
}

__global__ void reset_kernel(unsigned j) {
    int t = threadIdx.x;
    for (int i = t; i < NB1; i += blockDim.x) g_hist[i] = 0;
    if (t == 0) { g_rank = j; g_cand_cnt = 0; g_binT = 0; }
}

__global__ void hist1_kernel(const float4* __restrict__ in, int n4) {
    __shared__ unsigned sh[NB1];
    for (int i = threadIdx.x; i < NB1; i += blockDim.x) sh[i] = 0;
    __syncthreads();
    int stride = gridDim.x * blockDim.x;
    for (int i = blockIdx.x * blockDim.x + threadIdx.x; i < n4; i += stride) {
        float4 v = in[i];
        unsigned b;
        b = abskey(v.x) >> SHIFT1; if (b > NB1 - 1) b = NB1 - 1; atomicAdd(&sh[b], 1u);
        b = abskey(v.y) >> SHIFT1; if (b > NB1 - 1) b = NB1 - 1; atomicAdd(&sh[b], 1u);
        b = abskey(v.z) >> SHIFT1; if (b > NB1 - 1) b = NB1 - 1; atomicAdd(&sh[b], 1u);
        b = abskey(v.w) >> SHIFT1; if (b > NB1 - 1) b = NB1 - 1; atomicAdd(&sh[b], 1u);
    }
    __syncthreads();
    for (int i = threadIdx.x; i < NB1; i += blockDim.x) {
        unsigned c = sh[i];
        if (c) atomicAdd(&g_hist[i], c);
    }
}

// One block of 1024 threads: scan 8192 bins, find the bin containing rank.
__global__ void scan1_kernel() {
    __shared__ unsigned tot[1024];
    __shared__ unsigned s_bin, s_rank;
    int t = threadIdx.x;
    unsigned loc[NB1 / 1024];
    unsigned sum = 0;
    #pragma unroll
    for (int i = 0; i < NB1 / 1024; i++) { loc[i] = g_hist[t * (NB1 / 1024) + i]; sum += loc[i]; }
    unsigned rank = g_rank;       // read before any global write
    tot[t] = sum;
    __syncthreads();
    for (int off = 1; off < 1024; off <<= 1) {
        unsigned x = (t >= off) ? tot[t - off] : 0u;
        __syncthreads();
        tot[t] += x;
        __syncthreads();
    }
    unsigned run = tot[t] - sum;  // exclusive prefix
    #pragma unroll
    for (int i = 0; i < NB1 / 1024; i++) {
        if (run <= rank && rank < run + loc[i]) { s_bin = t * (NB1 / 1024) + i; s_rank = rank - run; }
        run += loc[i];
    }
    __syncthreads();
    if (t == 0) { g_binT = s_bin; g_rank = s_rank; }
}

// Write mask (bin > binT -> 1, bin < binT -> 0, bin == binT -> provisional 1)
// and compact threshold-bin (key, idx) via block-local smem buffers.
__global__ void mask_kernel(const float4* __restrict__ in, float4* __restrict__ out, int n4) {
    __shared__ unsigned s_idx[BLK_CAP];
    __shared__ unsigned s_key[BLK_CAP];
    __shared__ unsigned s_cnt, s_base;
    if (threadIdx.x == 0) s_cnt = 0;
    __syncthreads();
    const unsigned binT = g_binT;
    int stride = gridDim.x * blockDim.x;
    for (int i = blockIdx.x * blockDim.x + threadIdx.x; i < n4; i += stride) {
        float4 v = in[i];
        float4 r;
        unsigned base = ((unsigned)i) << 2;
        unsigned k, b;

        k = abskey(v.x); b = k >> SHIFT1; if (b > NB1 - 1) b = NB1 - 1;
        r.x = (b >= binT) ? 1.0f : 0.0f;
        if (b == binT) { unsigned p = atomicAdd(&s_cnt, 1u); if (p < BLK_CAP) { s_idx[p] = base + 0; s_key[p] = k; } }
        k = abskey(v.y); b = k >> SHIFT1; if (b > NB1 - 1) b = NB1 - 1;
        r.y = (b >= binT) ? 1.0f : 0.0f;
        if (b == binT) { unsigned p = atomicAdd(&s_cnt, 1u); if (p < BLK_CAP) { s_idx[p] = base + 1; s_key[p] = k; } }
        k = abskey(v.z); b = k >> SHIFT1; if (b > NB1 - 1) b = NB1 - 1;
        r.z = (b >= binT) ? 1.0f : 0.0f;
        if (b == binT) { unsigned p = atomicAdd(&s_cnt, 1u); if (p < BLK_CAP) { s_idx[p] = base + 2; s_key[p] = k; } }
        k = abskey(v.w); b = k >> SHIFT1; if (b > NB1 - 1) b = NB1 - 1;
        r.w = (b >= binT) ? 1.0f : 0.0f;
        if (b == binT) { unsigned p = atomicAdd(&s_cnt, 1u); if (p < BLK_CAP) { s_idx[p] = base + 3; s_key[p] = k; } }

        out[i] = r;
    }
    __syncthreads();
    if (threadIdx.x == 0) {
        unsigned c = s_cnt; if (c > BLK_CAP) c = BLK_CAP;
        s_cnt = c;
        s_base = atomicAdd(&g_cand_cnt, c);
    }
    __syncthreads();
    unsigned c = s_cnt, bpos = s_base;
    for (unsigned p = threadIdx.x; p < c; p += blockDim.x) {
        unsigned gp = bpos + p;
        if (gp < CAND_CAP) { g_cand_idx[gp] = s_idx[p]; g_cand_key[gp] = s_key[p]; }
    }
}

// Single block: select remaining 17 bits (8 then 9), zero sub-threshold
// candidates, resolve stable ties (first z equal keys by ascending index).
__global__ void cand_select_kernel(float* __restrict__ out) {
    __shared__ unsigned h[512];
    __shared__ unsigned s_sel, s_rank;
    __shared__ unsigned s_eq[EQ_CAP];
    __shared__ unsigned s_eqcnt;
    const int t = threadIdx.x;
    unsigned m = g_cand_cnt; if (m > CAND_CAP) m = CAND_CAP;
    unsigned rank = g_rank;
    const unsigned binT = g_binT;

    // ---- phase 1: bits 16..9 (256 bins) ----
    if (t < 512) h[t] = 0;
    if (t == 0) s_eqcnt = 0;
    __syncthreads();
    for (unsigned c = t; c < m; c += 1024)
        atomicAdd(&h[(g_cand_key[c] >> 9) & 255u], 1u);
    __syncthreads();
    unsigned v = (t < 256) ? h[t] : 0u;
    for (int off = 1; off < 256; off <<= 1) {
        unsigned x = (t < 256 && t >= off) ? h[t - off] : 0u;
        __syncthreads();
        if (t < 256) h[t] += x;
        __syncthreads();
    }
    if (t < 256) {
        unsigned incl = h[t], before = incl - v;
        if (before <= rank && rank < incl) { s_sel = t; s_rank = rank - before; }
    }
    __syncthreads();
    const unsigned b1 = s_sel;
    rank = s_rank;
    __syncthreads();

    // ---- phase 2: bits 8..0 (512 bins), candidates matching b1 ----
    if (t < 512) h[t] = 0;
    __syncthreads();
    for (unsigned c = t; c < m; c += 1024) {
        unsigned k = g_cand_key[c];
        if (((k >> 9) & 255u) == b1) atomicAdd(&h[k & 511u], 1u);
    }
    __syncthreads();
    v = (t < 512) ? h[t] : 0u;
    for (int off = 1; off < 512; off <<= 1) {
        unsigned x = (t < 512 && t >= off) ? h[t - off] : 0u;
        __syncthreads();
        if (t < 512) h[t] += x;
        __syncthreads();
    }
    if (t < 512) {
        unsigned incl = h[t], before = incl - v;
        if (before <= rank && rank < incl) { s_sel = t; s_rank = rank - before; }
    }
    __syncthreads();
    const unsigned T = (binT << SHIFT1) | (b1 << 9) | s_sel;
    const unsigned z = s_rank;

    // ---- phase 3: zero key < T, collect key == T ----
    for (unsigned c = t; c < m; c += 1024) {
        unsigned k = g_cand_key[c];
        if (k < T) {
            out[g_cand_idx[c]] = 0.0f;
        } else if (k == T) {
            unsigned p = atomicAdd(&s_eqcnt, 1u);
            if (p < EQ_CAP) s_eq[p] = g_cand_idx[c];
        }
    }
    __syncthreads();

    // ---- phase 4: stable tie-break (zero first z equals by flat index) ----
    unsigned eq = s_eqcnt; if (eq > EQ_CAP) eq = EQ_CAP;
    for (unsigned e = t; e < eq; e += 1024) {
        unsigned idx = s_eq[e];
        unsigned cnt = 0;
        for (unsigned s = 0; s < eq; s++) cnt += (s_eq[s] < idx) ? 1u : 0u;
        if (cnt < z) out[idx] = 0.0f;
    }
}

extern "C" void kernel_launch(void* const* d_in, const int* in_sizes, int n_in,
                              void* d_out, int out_size) {
    const float* A = (const float*)d_in[0];
    const float* B = (const float*)d_in[1];
    float* out = (float*)d_out;

    int n = in_sizes[0];
    int n4 = n / 4;
    unsigned j = (unsigned)((1.0 - 0.1) * (double)n);  // mirrors int((1-k)*n)

    const int HBLK = 2048, HTHR = 256;

    for (int m = 0; m < 2; m++) {
        const float* src = (m == 0) ? A : B;
        float* dst = out + (size_t)m * (size_t)n;

        reset_kernel<<<1, 1024>>>(j);
        hist1_kernel<<<HBLK, HTHR>>>((const float4*)src, n4);
        scan1_kernel<<<1, 1024>>>();
        mask_kernel<<<HBLK, HTHR>>>((const float4*)src, (float4*)dst, n4);
        cand_select_kernel<<<1, 1024>>>(dst);
    }
}

// round 3
// speedup vs baseline: 1.2677x; 1.2677x over previous
#include <cuda_runtime.h>
#include <cuda_bf16.h>

// Top-10% mask via radix select, both matrices processed concurrently.
// Stage 1: 8192-bin histogram of bits 29..17 (full read, both matrices).
// Stage 2: 2-block scan -> coarse threshold bin + residual rank.
// Stage 3: mask write + compaction of threshold-bin candidates (~131K/matrix).
// Stage 4: 131072-bin global histogram of candidates' low 17 bits (multi-block).
// Stage 5: 2-block scan -> exact threshold key T + residual rank z.
// Stage 6: zero candidates with key<T, collect key==T.
// Stage 7: stable tie-break (first z equal keys by ascending flat index -> 0).

#define NB1      8192
#define SHIFT1   17
#define NB17     131072
#define CAND_CAP 262144u
#define BLK_CAP  2048
#define EQ_CAP   8192

__device__ unsigned g_hist[2][NB1];
__device__ unsigned g_h17[2][NB17];
__device__ unsigned g_binT[2];
__device__ unsigned g_rank[2];     // after scan1: rank in bin; after scan17: z
__device__ unsigned g_keyT[2];
__device__ unsigned g_cand_idx[2][CAND_CAP];
__device__ unsigned g_cand_key[2][CAND_CAP];
__device__ unsigned g_cand_cnt[2];
__device__ unsigned g_eq[2][EQ_CAP];
__device__ unsigned g_eq_cnt[2];

__device__ __forceinline__ unsigned abskey(float v) {
    return __float_as_uint(v) & 0x7FFFFFFFu;
}

__global__ void reset_kernel(unsigned j) {
    int stride = gridDim.x * blockDim.x;
    int tid = blockIdx.x * blockDim.x + threadIdx.x;
    for (int i = tid; i < 2 * NB1; i += stride) ((unsigned*)g_hist)[i] = 0;
    for (int i = tid; i < 2 * NB17; i += stride) ((unsigned*)g_h17)[i] = 0;
    if (tid < 2) {
        g_rank[tid] = j;
        g_cand_cnt[tid] = 0;
        g_eq_cnt[tid] = 0;
        g_binT[tid] = 0;
        g_keyT[tid] = 0;
    }
}

__global__ void hist1_kernel(const float4* __restrict__ A,
                             const float4* __restrict__ B, int n4) {
    __shared__ unsigned sh[NB1];
    for (int i = threadIdx.x; i < NB1; i += blockDim.x) sh[i] = 0;
    __syncthreads();
    const int m = blockIdx.x & 1;
    const float4* __restrict__ in = m ? B : A;
    int stride = (gridDim.x >> 1) * blockDim.x;
    for (int i = (blockIdx.x >> 1) * blockDim.x + threadIdx.x; i < n4; i += stride) {
        float4 v = in[i];
        unsigned b;
        b = abskey(v.x) >> SHIFT1; b = min(b, (unsigned)(NB1 - 1)); atomicAdd(&sh[b], 1u);
        b = abskey(v.y) >> SHIFT1; b = min(b, (unsigned)(NB1 - 1)); atomicAdd(&sh[b], 1u);
        b = abskey(v.z) >> SHIFT1; b = min(b, (unsigned)(NB1 - 1)); atomicAdd(&sh[b], 1u);
        b = abskey(v.w) >> SHIFT1; b = min(b, (unsigned)(NB1 - 1)); atomicAdd(&sh[b], 1u);
    }
    __syncthreads();
    for (int i = threadIdx.x; i < NB1; i += blockDim.x) {
        unsigned c = sh[i];
        if (c) atomicAdd(&g_hist[m][i], c);
    }
}

// 2 blocks (one per matrix), 1024 threads: find coarse bin containing rank.
__global__ void scan1_kernel() {
    __shared__ unsigned tot[1024];
    __shared__ unsigned s_bin, s_rank;
    const int m = blockIdx.x;
    const int t = threadIdx.x;
    unsigned loc[NB1 / 1024];
    unsigned sum = 0;
    #pragma unroll
    for (int i = 0; i < NB1 / 1024; i++) {
        loc[i] = g_hist[m][t * (NB1 / 1024) + i];
        sum += loc[i];
    }
    unsigned rank = g_rank[m];
    tot[t] = sum;
    __syncthreads();
    for (int off = 1; off < 1024; off <<= 1) {
        unsigned x = (t >= off) ? tot[t - off] : 0u;
        __syncthreads();
        tot[t] += x;
        __syncthreads();
    }
    unsigned run = tot[t] - sum;
    #pragma unroll
    for (int i = 0; i < NB1 / 1024; i++) {
        if (run <= rank && rank < run + loc[i]) {
            s_bin = t * (NB1 / 1024) + i;
            s_rank = rank - run;
        }
        run += loc[i];
    }
    __syncthreads();
    if (t == 0) { g_binT[m] = s_bin; g_rank[m] = s_rank; }
}

__global__ void mask_kernel(const float4* __restrict__ A,
                            const float4* __restrict__ B,
                            float4* __restrict__ out, int n4) {
    __shared__ unsigned s_idx[BLK_CAP];
    __shared__ unsigned s_key[BLK_CAP];
    __shared__ unsigned s_cnt, s_base;
    if (threadIdx.x == 0) s_cnt = 0;
    __syncthreads();
    const int m = blockIdx.x & 1;
    const float4* __restrict__ in = m ? B : A;
    float4* __restrict__ dst = out + (size_t)m * (size_t)n4;
    const unsigned binT = g_binT[m];
    int stride = (gridDim.x >> 1) * blockDim.x;
    for (int i = (blockIdx.x >> 1) * blockDim.x + threadIdx.x; i < n4; i += stride) {
        float4 v = in[i];
        float4 r;
        unsigned base = ((unsigned)i) << 2;
        unsigned k, b;

        k = abskey(v.x); b = min(k >> SHIFT1, (unsigned)(NB1 - 1));
        r.x = (b >= binT) ? 1.0f : 0.0f;
        if (b == binT) { unsigned p = atomicAdd(&s_cnt, 1u); if (p < BLK_CAP) { s_idx[p] = base; s_key[p] = k; } }
        k = abskey(v.y); b = min(k >> SHIFT1, (unsigned)(NB1 - 1));
        r.y = (b >= binT) ? 1.0f : 0.0f;
        if (b == binT) { unsigned p = atomicAdd(&s_cnt, 1u); if (p < BLK_CAP) { s_idx[p] = base + 1; s_key[p] = k; } }
        k = abskey(v.z); b = min(k >> SHIFT1, (unsigned)(NB1 - 1));
        r.z = (b >= binT) ? 1.0f : 0.0f;
        if (b == binT) { unsigned p = atomicAdd(&s_cnt, 1u); if (p < BLK_CAP) { s_idx[p] = base + 2; s_key[p] = k; } }
        k = abskey(v.w); b = min(k >> SHIFT1, (unsigned)(NB1 - 1));
        r.w = (b >= binT) ? 1.0f : 0.0f;
        if (b == binT) { unsigned p = atomicAdd(&s_cnt, 1u); if (p < BLK_CAP) { s_idx[p] = base + 3; s_key[p] = k; } }

        dst[i] = r;
    }
    __syncthreads();
    if (threadIdx.x == 0) {
        unsigned c = min(s_cnt, (unsigned)BLK_CAP);
        s_cnt = c;
        s_base = atomicAdd(&g_cand_cnt[m], c);
    }
    __syncthreads();
    unsigned c = s_cnt, bpos = s_base;
    for (unsigned p = threadIdx.x; p < c; p += blockDim.x) {
        unsigned gp = bpos + p;
        if (gp < CAND_CAP) { g_cand_idx[m][gp] = s_idx[p]; g_cand_key[m][gp] = s_key[p]; }
    }
}

// Multi-block: histogram candidates' low 17 bits into global bins.
__global__ void hist17_kernel() {
    const int m = blockIdx.x & 1;
    unsigned cnt = min(g_cand_cnt[m], CAND_CAP);
    int stride = (gridDim.x >> 1) * blockDim.x;
    for (unsigned c = (blockIdx.x >> 1) * blockDim.x + threadIdx.x; c < cnt; c += stride)
        atomicAdd(&g_h17[m][g_cand_key[m][c] & (NB17 - 1)], 1u);
}

// 2 blocks: scan 131072 bins -> exact threshold key + residual z.
__global__ void scan17_kernel() {
    __shared__ unsigned tot[1024];
    __shared__ unsigned s_key, s_z;
    const int m = blockIdx.x;
    const int t = threadIdx.x;
    const unsigned* __restrict__ h = g_h17[m];
    const int C = NB17 / 1024;  // 128 bins per thread, contiguous
    unsigned rank = g_rank[m];
    unsigned sum = 0;
    for (int i = 0; i < C; i++) sum += h[t * C + i];
    tot[t] = sum;
    __syncthreads();
    for (int off = 1; off < 1024; off <<= 1) {
        unsigned x = (t >= off) ? tot[t - off] : 0u;
        __syncthreads();
        tot[t] += x;
        __syncthreads();
    }
    unsigned run = tot[t] - sum;
    if (run <= rank && rank < run + sum) {
        unsigned r = rank - run;
        for (int i = 0; i < C; i++) {
            unsigned c = h[t * C + i];
            if (r < c) { s_key = (g_binT[m] << SHIFT1) | (unsigned)(t * C + i); s_z = r; break; }
            r -= c;
        }
    }
    __syncthreads();
    if (t == 0) { g_keyT[m] = s_key; g_rank[m] = s_z; }
}

// Multi-block: zero candidates below T, collect equals.
__global__ void final_kernel(float* __restrict__ out, int n) {
    const int m = blockIdx.x & 1;
    float* __restrict__ dst = out + (size_t)m * (size_t)n;
    const unsigned T = g_keyT[m];
    unsigned cnt = min(g_cand_cnt[m], CAND_CAP);
    int stride = (gridDim.x >> 1) * blockDim.x;
    for (unsigned c = (blockIdx.x >> 1) * blockDim.x + threadIdx.x; c < cnt; c += stride) {
        unsigned k = g_cand_key[m][c];
        if (k < T) {
            dst[g_cand_idx[m][c]] = 0.0f;
        } else if (k == T) {
            unsigned p = atomicAdd(&g_eq_cnt[m], 1u);
            if (p < EQ_CAP) g_eq[m][p] = g_cand_idx[m][c];
        }
    }
}

// 2 blocks: among T-equal elements, zero the first z by ascending flat index.
__global__ void fixup_kernel(float* __restrict__ out, int n) {
    const int m = blockIdx.x;
    float* __restrict__ dst = out + (size_t)m * (size_t)n;
    unsigned eq = min(g_eq_cnt[m], (unsigned)EQ_CAP);
    unsigned z = g_rank[m];
    for (unsigned e = threadIdx.x; e < eq; e += blockDim.x) {
        unsigned idx = g_eq[m][e];
        unsigned cnt = 0;
        for (unsigned s = 0; s < eq; s++) cnt += (g_eq[m][s] < idx) ? 1u : 0u;
        if (cnt < z) dst[idx] = 0.0f;
    }
}

extern "C" void kernel_launch(void* const* d_in, const int* in_sizes, int n_in,
                              void* d_out, int out_size) {
    const float* A = (const float*)d_in[0];
    const float* B = (const float*)d_in[1];
    float* out = (float*)d_out;

    int n = in_sizes[0];
    int n4 = n / 4;
    unsigned j = (unsigned)((1.0 - 0.1) * (double)n);  // mirrors int((1-k)*n)

    reset_kernel<<<64, 1024>>>(j);
    hist1_kernel<<<2048, 512>>>((const float4*)A, (const float4*)B, n4);
    scan1_kernel<<<2, 1024>>>();
    mask_kernel<<<4096, 256>>>((const float4*)A, (const float4*)B, (float4*)out, n4);
    hist17_kernel<<<256, 256>>>();
    scan17_kernel<<<2, 1024>>>();
    final_kernel<<<256, 256>>>(out, n);
    fixup_kernel<<<2, 1024>>>(out, n);
}

// round 4
// speedup vs baseline: 2.5417x; 2.0050x over previous
#include <cuda_runtime.h>
#include <cuda_bf16.h>

// Top-10% mask via radix select; both matrices concurrent in every kernel.
// S1: 8192-bin histogram of bits 29..17 (full read).
// S2: 2-block scan -> coarse bin + residual rank.
// S3: mask write + compact threshold-bin candidates (~131K/matrix).
// S4: 2-block candidate pass, bits 16..7 (1024 smem bins) -> sub-bin+rank.
// S5: 2-block candidate pass, bits 6..0 (128 smem bins) -> exact T + z.
// S6: zero candidates < T, collect == T.   S7: stable tie fixup.

#define NB1      8192
#define SHIFT1   17
#define CAND_CAP 262144u
#define BLK_CAP  2048
#define EQ_CAP   8192

__device__ unsigned g_hist[2][NB1];
__device__ unsigned g_binT[2];
__device__ unsigned g_selA[2];
__device__ unsigned g_rank[2];
__device__ unsigned g_keyT[2];
__device__ unsigned g_cand_idx[2][CAND_CAP];
__device__ unsigned g_cand_key[2][CAND_CAP];
__device__ unsigned g_cand_cnt[2];
__device__ unsigned g_eq[2][EQ_CAP];
__device__ unsigned g_eq_cnt[2];

__device__ __forceinline__ unsigned abskey(float v) {
    return __float_as_uint(v) & 0x7FFFFFFFu;
}

__global__ void reset_kernel(unsigned j) {
    int tid = blockIdx.x * blockDim.x + threadIdx.x;
    int stride = gridDim.x * blockDim.x;
    for (int i = tid; i < 2 * NB1; i += stride) ((unsigned*)g_hist)[i] = 0;
    if (tid < 2) {
        g_rank[tid] = j;
        g_cand_cnt[tid] = 0;
        g_eq_cnt[tid] = 0;
    }
}

__global__ void hist1_kernel(const float4* __restrict__ A,
                             const float4* __restrict__ B, int n4) {
    __shared__ unsigned sh[NB1];
    for (int i = threadIdx.x; i < NB1; i += blockDim.x) sh[i] = 0;
    __syncthreads();
    const int m = blockIdx.x & 1;
    const float4* __restrict__ in = m ? B : A;
    int stride = (gridDim.x >> 1) * blockDim.x;
    for (int i = (blockIdx.x >> 1) * blockDim.x + threadIdx.x; i < n4; i += stride) {
        float4 v = in[i];
        atomicAdd(&sh[abskey(v.x) >> SHIFT1], 1u);
        atomicAdd(&sh[abskey(v.y) >> SHIFT1], 1u);
        atomicAdd(&sh[abskey(v.z) >> SHIFT1], 1u);
        atomicAdd(&sh[abskey(v.w) >> SHIFT1], 1u);
    }
    __syncthreads();
    for (int i = threadIdx.x; i < NB1; i += blockDim.x) {
        unsigned c = sh[i];
        if (c) atomicAdd(&g_hist[m][i], c);
    }
}

// 2 blocks (one per matrix), 1024 threads: coarse bin containing rank.
__global__ void scan1_kernel() {
    __shared__ unsigned tot[1024];
    __shared__ unsigned s_bin, s_rank;
    const int m = blockIdx.x;
    const int t = threadIdx.x;
    unsigned loc[NB1 / 1024];
    unsigned sum = 0;
    #pragma unroll
    for (int i = 0; i < NB1 / 1024; i++) {
        loc[i] = g_hist[m][t * (NB1 / 1024) + i];
        sum += loc[i];
    }
    unsigned rank = g_rank[m];
    tot[t] = sum;
    __syncthreads();
    for (int off = 1; off < 1024; off <<= 1) {
        unsigned x = (t >= off) ? tot[t - off] : 0u;
        __syncthreads();
        tot[t] += x;
        __syncthreads();
    }
    unsigned run = tot[t] - sum;
    #pragma unroll
    for (int i = 0; i < NB1 / 1024; i++) {
        if (run <= rank && rank < run + loc[i]) {
            s_bin = t * (NB1 / 1024) + i;
            s_rank = rank - run;
        }
        run += loc[i];
    }
    __syncthreads();
    if (t == 0) { g_binT[m] = s_bin; g_rank[m] = s_rank; }
}

__global__ void mask_kernel(const float4* __restrict__ A,
                            const float4* __restrict__ B,
                            float4* __restrict__ out, int n4) {
    __shared__ unsigned s_idx[BLK_CAP];
    __shared__ unsigned s_key[BLK_CAP];
    __shared__ unsigned s_cnt, s_base;
    if (threadIdx.x == 0) s_cnt = 0;
    __syncthreads();
    const int m = blockIdx.x & 1;
    const float4* __restrict__ in = m ? B : A;
    float4* __restrict__ dst = out + (size_t)m * (size_t)n4;
    const unsigned keyLo = g_binT[m] << SHIFT1;
    const unsigned keyHi = keyLo + (1u << SHIFT1);
    int stride = (gridDim.x >> 1) * blockDim.x;
    for (int i = (blockIdx.x >> 1) * blockDim.x + threadIdx.x; i < n4; i += stride) {
        float4 v = in[i];
        float4 r;
        unsigned base = ((unsigned)i) << 2;
        unsigned k;

        k = abskey(v.x);
        r.x = (k >= keyLo) ? 1.0f : 0.0f;
        if (k >= keyLo && k < keyHi) { unsigned p = atomicAdd(&s_cnt, 1u); if (p < BLK_CAP) { s_idx[p] = base; s_key[p] = k; } }
        k = abskey(v.y);
        r.y = (k >= keyLo) ? 1.0f : 0.0f;
        if (k >= keyLo && k < keyHi) { unsigned p = atomicAdd(&s_cnt, 1u); if (p < BLK_CAP) { s_idx[p] = base + 1; s_key[p] = k; } }
        k = abskey(v.z);
        r.z = (k >= keyLo) ? 1.0f : 0.0f;
        if (k >= keyLo && k < keyHi) { unsigned p = atomicAdd(&s_cnt, 1u); if (p < BLK_CAP) { s_idx[p] = base + 2; s_key[p] = k; } }
        k = abskey(v.w);
        r.w = (k >= keyLo) ? 1.0f : 0.0f;
        if (k >= keyLo && k < keyHi) { unsigned p = atomicAdd(&s_cnt, 1u); if (p < BLK_CAP) { s_idx[p] = base + 3; s_key[p] = k; } }

        dst[i] = r;
    }
    __syncthreads();
    if (threadIdx.x == 0) {
        unsigned c = min(s_cnt, (unsigned)BLK_CAP);
        s_cnt = c;
        s_base = atomicAdd(&g_cand_cnt[m], c);
    }
    __syncthreads();
    unsigned c = s_cnt, bpos = s_base;
    for (unsigned p = threadIdx.x; p < c; p += blockDim.x) {
        unsigned gp = bpos + p;
        if (gp < CAND_CAP) { g_cand_idx[m][gp] = s_idx[p]; g_cand_key[m][gp] = s_key[p]; }
    }
}

// 2 blocks: histogram candidates' bits 16..7 (1024 bins), scan, select.
__global__ void candA_kernel() {
    __shared__ unsigned h[1024];
    __shared__ unsigned s_sel, s_rank;
    const int m = blockIdx.x;
    const int t = threadIdx.x;
    h[t] = 0;
    __syncthreads();
    unsigned cnt = min(g_cand_cnt[m], CAND_CAP);
    unsigned rank = g_rank[m];
    const unsigned* __restrict__ keys = g_cand_key[m];
    for (unsigned c = t; c < cnt; c += 1024)
        atomicAdd(&h[(keys[c] >> 7) & 1023u], 1u);
    __syncthreads();
    unsigned v = h[t];
    for (int off = 1; off < 1024; off <<= 1) {
        unsigned x = (t >= off) ? h[t - off] : 0u;
        __syncthreads();
        h[t] += x;
        __syncthreads();
    }
    unsigned incl = h[t], before = incl - v;
    if (before <= rank && rank < incl) { s_sel = t; s_rank = rank - before; }
    __syncthreads();
    if (t == 0) { g_selA[m] = s_sel; g_rank[m] = s_rank; }
}

// 2 blocks: histogram matching candidates' bits 6..0 (128 bins) -> T, z.
__global__ void candB_kernel() {
    __shared__ unsigned h[128];
    __shared__ unsigned s_sel, s_rank;
    const int m = blockIdx.x;
    const int t = threadIdx.x;
    if (t < 128) h[t] = 0;
    __syncthreads();
    unsigned cnt = min(g_cand_cnt[m], CAND_CAP);
    unsigned rank = g_rank[m];
    const unsigned selA = g_selA[m];
    const unsigned* __restrict__ keys = g_cand_key[m];
    for (unsigned c = t; c < cnt; c += 1024) {
        unsigned k = keys[c];
        if (((k >> 7) & 1023u) == selA) atomicAdd(&h[k & 127u], 1u);
    }
    __syncthreads();
    unsigned v = (t < 128) ? h[t] : 0u;
    for (int off = 1; off < 128; off <<= 1) {
        unsigned x = (t < 128 && t >= off) ? h[t - off] : 0u;
        __syncthreads();
        if (t < 128) h[t] += x;
        __syncthreads();
    }
    if (t < 128) {
        unsigned incl = h[t], before = incl - v;
        if (before <= rank && rank < incl) { s_sel = t; s_rank = rank - before; }
    }
    __syncthreads();
    if (t == 0) {
        g_keyT[m] = (g_binT[m] << SHIFT1) | (selA << 7) | s_sel;
        g_rank[m] = s_rank;   // z
    }
}

// Multi-block: zero candidates < T, collect == T.
__global__ void final_kernel(float* __restrict__ out, int n) {
    const int m = blockIdx.x & 1;
    float* __restrict__ dst = out + (size_t)m * (size_t)n;
    const unsigned T = g_keyT[m];
    unsigned cnt = min(g_cand_cnt[m], CAND_CAP);
    int stride = (gridDim.x >> 1) * blockDim.x;
    for (unsigned c = (blockIdx.x >> 1) * blockDim.x + threadIdx.x; c < cnt; c += stride) {
        unsigned k = g_cand_key[m][c];
        if (k < T) {
            dst[g_cand_idx[m][c]] = 0.0f;
        } else if (k == T) {
            unsigned p = atomicAdd(&g_eq_cnt[m], 1u);
            if (p < EQ_CAP) g_eq[m][p] = g_cand_idx[m][c];
        }
    }
}

// 2 blocks: among T-equal elements, zero the first z by ascending flat index.
__global__ void fixup_kernel(float* __restrict__ out, int n) {
    const int m = blockIdx.x;
    float* __restrict__ dst = out + (size_t)m * (size_t)n;
    unsigned eq = min(g_eq_cnt[m], (unsigned)EQ_CAP);
    unsigned z = g_rank[m];
    for (unsigned e = threadIdx.x; e < eq; e += blockDim.x) {
        unsigned idx = g_eq[m][e];
        unsigned cnt = 0;
        for (unsigned s = 0; s < eq; s++) cnt += (g_eq[m][s] < idx) ? 1u : 0u;
        if (cnt < z) dst[idx] = 0.0f;
    }
}

extern "C" void kernel_launch(void* const* d_in, const int* in_sizes, int n_in,
                              void* d_out, int out_size) {
    const float* A = (const float*)d_in[0];
    const float* B = (const float*)d_in[1];
    float* out = (float*)d_out;

    int n = in_sizes[0];
    int n4 = n / 4;
    unsigned j = (unsigned)((1.0 - 0.1) * (double)n);  // mirrors int((1-k)*n)

    reset_kernel<<<16, 1024>>>(j);
    hist1_kernel<<<2048, 512>>>((const float4*)A, (const float4*)B, n4);
    scan1_kernel<<<2, 1024>>>();
    mask_kernel<<<4096, 256>>>((const float4*)A, (const float4*)B, (float4*)out, n4);
    candA_kernel<<<2, 1024>>>();
    candB_kernel<<<2, 1024>>>();
    final_kernel<<<256, 256>>>(out, n);
    fixup_kernel<<<2, 1024>>>(out, n);
}